// round 13
// baseline (speedup 1.0000x reference)
#include <cuda_runtime.h>
#include <cuda_fp16.h>
#include <math.h>
#include <stdint.h>

// B=4, M=N=2048, D_QK=D_V=256, H=8.  All fp32 in/out.
// Weight-composed fp16 pipeline (round-11 structure):
//   S  = q (Wq_h Wk_h^T) k^T  -> precompute M^T, Qm = q@M, flash vs raw k
//   out = sum_h (P v) (Wv_h Wu_h) -> precompute N^T hi/lo, flash PV vs raw v,
//         out-projection = Pv @ N (3-term hi/lo, split-K=2)
// Flash uses FIXED-max softmax (logits O(1), exp2 overflow-safe); this is
// the ONLY delta vs the 858us round-11 kernel.

typedef __half f16;

// ------------------------- scratch (static, no allocation) ---------------
__device__ f16 g_qh[8192L*256], g_kh[8192L*256];
__device__ f16 g_Wqh[256L*2048], g_Wql[256L*2048];
__device__ f16 g_Wkh[256L*2048], g_Wkl[256L*2048];
__device__ f16 g_Wvh[256L*2048], g_Wvl[256L*2048];
__device__ f16 g_WuTh[256L*2048], g_WuTl[256L*2048];
__device__ f16 g_MT[2048L*256];                    // (Wq_h Wk_h^T)^T stacked
__device__ f16 g_NTh[256L*2048], g_NTl[256L*2048]; // (Wv_h Wu_h)^T stacked
__device__ f16 g_vT[4L*256*2048];                  // per-batch v^T [256 d][2048 tok]
__device__ f16 g_Qm[8192L*2048];
__device__ f16 g_Oh[8192L*2048], g_Ol[8192L*2048];
__device__ float g_Part[2L*8192*256];              // split-K partials

// ------------------------- helpers ---------------------------------------
__device__ __forceinline__ uint32_t smem_u32(const void* p) {
    uint32_t a;
    asm("{ .reg .u64 t; cvta.to.shared.u64 t, %1; cvt.u32.u64 %0, t; }" : "=r"(a) : "l"(p));
    return a;
}
__device__ __forceinline__ void cpasync16(uint32_t s, const void* g) {
    asm volatile("cp.async.cg.shared.global [%0], [%1], 16;" :: "r"(s), "l"(g) : "memory");
}
__device__ __forceinline__ void cp_commit() {
    asm volatile("cp.async.commit_group;" ::: "memory");
}
__device__ __forceinline__ void cp_wait0() { asm volatile("cp.async.wait_group 0;" ::: "memory"); }
__device__ __forceinline__ void cp_wait1() { asm volatile("cp.async.wait_group 1;" ::: "memory"); }
__device__ __forceinline__ void cp_wait2() { asm volatile("cp.async.wait_group 2;" ::: "memory"); }
__device__ __forceinline__ void ldsm4(uint32_t* r, uint32_t addr) {
    asm volatile("ldmatrix.sync.aligned.m8n8.x4.shared.b16 {%0,%1,%2,%3}, [%4];"
                 : "=r"(r[0]), "=r"(r[1]), "=r"(r[2]), "=r"(r[3]) : "r"(addr));
}
__device__ __forceinline__ void mma16816(float* d, const uint32_t* a,
                                         uint32_t b0, uint32_t b1) {
    asm volatile("mma.sync.aligned.m16n8k16.row.col.f32.f16.f16.f32 "
                 "{%0,%1,%2,%3}, {%4,%5,%6,%7}, {%8,%9}, {%0,%1,%2,%3};"
                 : "+f"(d[0]), "+f"(d[1]), "+f"(d[2]), "+f"(d[3])
                 : "r"(a[0]), "r"(a[1]), "r"(a[2]), "r"(a[3]), "r"(b0), "r"(b1));
}
__device__ __forceinline__ float ex2(float x) {
    float r;
    asm("ex2.approx.f32 %0, %1;" : "=f"(r) : "f"(x));
    return r;
}
__device__ __forceinline__ uint32_t pack_f16x2(float lo, float hi) {
    uint32_t r;
    asm("cvt.rn.f16x2.f32 %0, %1, %2;" : "=r"(r) : "f"(hi), "f"(lo));
    return r;
}
// tile layout: rows x 64B; two rows per 128B line + SW128 xor.
__device__ __forceinline__ uint32_t tile_off(int row, int kb) {
    uint32_t o = ((uint32_t)(row >> 1) << 7) | ((uint32_t)(row & 1) << 6) | (uint32_t)kb;
    return o ^ ((o >> 3) & 0x70);
}
// 256B-row tile: row-local xor swizzle, conflict-free ldmatrix
__device__ __forceinline__ uint32_t koff2(int row, uint32_t cb) {
    return (uint32_t)row * 256 + (cb ^ ((uint32_t)(row & 7) << 4));
}
// 512B-row tile (persistent Q)
__device__ __forceinline__ uint32_t q_off(int row, uint32_t colb) {
    return (uint32_t)row * 512 + (colb ^ ((uint32_t)(row & 7) << 4));
}
__device__ __forceinline__ void split_store16(float v, f16* ph, f16* pl) {
    f16 h = __float2half_rn(v);
    *ph = h;
    *pl = __float2half_rn(v - __half2float(h));
}

// ------------------------- convert fp32 -> fp16 (q,k fused) --------------
__global__ __launch_bounds__(256)
void convert2(const float* __restrict__ x0, const float* __restrict__ x1,
              f16* __restrict__ h0, f16* __restrict__ h1)
{
    const int z = blockIdx.z;
    const float* x = (z == 0) ? x0 : x1;
    f16* h = (z == 0) ? h0 : h1;
    size_t base = ((size_t)blockIdx.x * 256 + threadIdx.x) * 8;
#pragma unroll
    for (int j = 0; j < 8; j++)
        h[base + j] = __float2half_rn(x[base + j]);
}

// three fp32 tensors -> hi/lo fp16 planes, no transpose (Wq, Wk, Wv)
__global__ __launch_bounds__(256)
void convhl3(const float* __restrict__ w0, const float* __restrict__ w1,
             const float* __restrict__ w2,
             f16* __restrict__ h0, f16* __restrict__ l0,
             f16* __restrict__ h1, f16* __restrict__ l1,
             f16* __restrict__ h2, f16* __restrict__ l2)
{
    const int z = blockIdx.z;
    const float* x = (z == 0) ? w0 : (z == 1) ? w1 : w2;
    f16* h = (z == 0) ? h0 : (z == 1) ? h1 : h2;
    f16* l = (z == 0) ? l0 : (z == 1) ? l1 : l2;
    size_t base = ((size_t)blockIdx.x * 256 + threadIdx.x) * 8;
#pragma unroll
    for (int j = 0; j < 8; j++)
        split_store16(x[base + j], h + base + j, l + base + j);
}

// Wu transpose -> hi/lo fp16 planes
__global__ __launch_bounds__(256)
void transpose_hilo(const float* __restrict__ in, f16* __restrict__ oh,
                    f16* __restrict__ ol, int R, int C)
{
    __shared__ float t[32][33];
    int c0 = blockIdx.x * 32, r0 = blockIdx.y * 32;
    int x = threadIdx.x & 31, y = (threadIdx.x >> 5) * 4;
#pragma unroll
    for (int i = 0; i < 4; i++)
        t[y + i][x] = in[(size_t)(r0 + y + i) * C + c0 + x];
    __syncthreads();
#pragma unroll
    for (int i = 0; i < 4; i++) {
        size_t o = (size_t)(c0 + y + i) * R + r0 + x;
        split_store16(t[x][y + i], oh + o, ol + o);
    }
}

// per-batch transpose: v fp32 [2048 tok, 256 d] -> vT fp16 [256 d, 2048 tok]
__global__ __launch_bounds__(256)
void transpose_vf16(const float* __restrict__ in, f16* __restrict__ out)
{
    __shared__ float t[32][33];
    const size_t ioff = (size_t)blockIdx.z * 2048 * 256;
    const size_t ooff = (size_t)blockIdx.z * 256 * 2048;
    int c0 = blockIdx.x * 32;   // d block
    int r0 = blockIdx.y * 32;   // tok block
    int x = threadIdx.x & 31, y = (threadIdx.x >> 5) * 4;
#pragma unroll
    for (int i = 0; i < 4; i++)
        t[y + i][x] = in[ioff + (size_t)(r0 + y + i) * 256 + c0 + x];
    __syncthreads();
#pragma unroll
    for (int i = 0; i < 4; i++)
        out[ooff + (size_t)(c0 + y + i) * 2048 + r0 + x] =
            __float2half_rn(t[x][y + i]);
}

// ------------------------- mma.sync batched GEMM -------------------------
// C[M,N] = alpha * A[M,K] @ B[N,K]^T, fp16 K-major operands.
// TERMS: 1 = Ah*Bh; 3 = + Ah*Bl + Al*Bh.
// OUTMODE: 0 = f32 (Cf), 2 = hi/lo fp16 (Ch,Cl), 3 = hi fp16 (Ch).
// blockIdx.z: A/B element offset z*kzoff, output element offset z*czoff.
template<int OUTMODE, int TERMS>
__global__ __launch_bounds__(256)
void bgemm_mma(int K,
               const f16* __restrict__ Ah, const f16* __restrict__ Al, int lda,
               const f16* __restrict__ Bh, const f16* __restrict__ Bl, int ldb,
               float* __restrict__ Cf, f16* __restrict__ Ch, f16* __restrict__ Cl,
               int ldc, float alpha, long kzoff, long czoff)
{
    extern __shared__ char smem_raw[];
    const uint32_t base = (smem_u32(smem_raw) + 1023) & ~1023u;
    constexpr uint32_t BUF = (TERMS == 3) ? 32768 : 16384;
    constexpr uint32_t OFF_B = (TERMS == 3) ? 16384 : 8192;

    const long kz = (long)blockIdx.z * kzoff;
    Ah += kz; Bh += kz;
    if (TERMS == 3) { Al += kz; Bl += kz; }
    const long cz = (long)blockIdx.z * czoff;
    if (OUTMODE == 0) Cf += cz;
    else { Ch += cz; if (OUTMODE == 2) Cl += cz; }

    const int tid  = threadIdx.x;
    const int lane = tid & 31;
    const int warp = tid >> 5;
    const int brow = blockIdx.y * 128;
    const int bcol = blockIdx.x * 128;
    const int wr   = (warp >> 2) * 64;
    const int wc   = (warp & 3) * 32;

    const int r0u = (tid * 2) >> 2,      j0u = (tid * 2) & 3;
    const int r1u = (tid * 2 + 1) >> 2,  j1u = (tid * 2 + 1) & 3;

    float acc[4][4][4];
#pragma unroll
    for (int mi = 0; mi < 4; mi++)
#pragma unroll
        for (int ni = 0; ni < 4; ni++)
#pragma unroll
            for (int r = 0; r < 4; r++) acc[mi][ni][r] = 0.0f;

    const int nchunk = K >> 5;

    auto issue = [&](int c, int buf) {
        const int k0 = c << 5;
        const uint32_t sb = base + buf * BUF;
        const uint32_t s0 = tile_off(r0u, j0u * 16);
        const uint32_t s1 = tile_off(r1u, j1u * 16);
        const size_t ga0 = (size_t)(brow + r0u) * lda + k0 + j0u * 8;
        const size_t ga1 = (size_t)(brow + r1u) * lda + k0 + j1u * 8;
        const size_t gb0 = (size_t)(bcol + r0u) * ldb + k0 + j0u * 8;
        const size_t gb1 = (size_t)(bcol + r1u) * ldb + k0 + j1u * 8;
        cpasync16(sb + s0, Ah + ga0);
        cpasync16(sb + s1, Ah + ga1);
        cpasync16(sb + OFF_B + s0, Bh + gb0);
        cpasync16(sb + OFF_B + s1, Bh + gb1);
        if (TERMS == 3) {
            cpasync16(sb +  8192 + s0, Al + ga0);
            cpasync16(sb +  8192 + s1, Al + ga1);
            cpasync16(sb + 24576 + s0, Bl + gb0);
            cpasync16(sb + 24576 + s1, Bl + gb1);
        }
        cp_commit();
    };

    issue(0, 0);
    issue(1, 1);

    int bufc = 0;
    for (int c = 0; c < nchunk; c++) {
        if (c + 1 < nchunk) cp_wait1(); else cp_wait0();
        __syncthreads();
        if (c + 2 < nchunk) {
            int nb = bufc + 2; if (nb >= 3) nb -= 3;
            issue(c + 2, nb);
        }

        const uint32_t sb = base + bufc * BUF;
#pragma unroll
        for (int ks = 0; ks < 2; ks++) {
            const int kb = ks * 32 + (lane >> 4) * 16;
            uint32_t bh[2][4], bl[2][4];
#pragma unroll
            for (int t16 = 0; t16 < 2; t16++) {
                const uint32_t so = tile_off(wc + t16 * 16 + (lane & 15), kb);
                ldsm4(bh[t16], sb + OFF_B + so);
                if (TERMS == 3) ldsm4(bl[t16], sb + 24576 + so);
            }
#pragma unroll
            for (int mi = 0; mi < 4; mi++) {
                uint32_t ah[4], al[4];
                const uint32_t so = tile_off(wr + mi * 16 + (lane & 15), kb);
                ldsm4(ah, sb + so);
                if (TERMS == 3) ldsm4(al, sb + 8192 + so);
#pragma unroll
                for (int ni = 0; ni < 4; ni++) {
                    const int t16 = ni >> 1, sub = ni & 1;
                    const uint32_t bh0 = bh[t16][sub], bh1 = bh[t16][2 + sub];
                    mma16816(acc[mi][ni], ah, bh0, bh1);
                    if (TERMS == 3) {
                        const uint32_t bl0 = bl[t16][sub], bl1 = bl[t16][2 + sub];
                        mma16816(acc[mi][ni], ah, bl0, bl1);
                        mma16816(acc[mi][ni], al, bh0, bh1);
                    }
                }
            }
        }
        if (++bufc == 3) bufc = 0;
    }

#pragma unroll
    for (int mi = 0; mi < 4; mi++) {
#pragma unroll
        for (int half = 0; half < 2; half++) {
            const int row = brow + wr + mi * 16 + (lane >> 2) + half * 8;
#pragma unroll
            for (int ni = 0; ni < 4; ni++) {
                const int col = bcol + wc + ni * 8 + (lane & 3) * 2;
                float v0 = acc[mi][ni][half * 2 + 0] * alpha;
                float v1 = acc[mi][ni][half * 2 + 1] * alpha;
                if (OUTMODE == 0) {
                    float2 o; o.x = v0; o.y = v1;
                    *(float2*)(Cf + (size_t)row * ldc + col) = o;
                } else if (OUTMODE == 3) {
                    *(uint32_t*)(Ch + (size_t)row * ldc + col) = pack_f16x2(v0, v1);
                } else {
                    const size_t off = (size_t)row * ldc + col;
                    f16 h0 = __float2half_rn(v0), h1 = __float2half_rn(v1);
                    *(__half2*)(Ch + off) = __halves2half2(h0, h1);
                    *(__half2*)(Cl + off) = __halves2half2(
                        __float2half_rn(v0 - __half2float(h0)),
                        __float2half_rn(v1 - __half2float(h1)));
                }
            }
        }
    }
}

// ------------------------- split-K reduce + bias -------------------------
__global__ __launch_bounds__(256)
void reduce_add(const float* __restrict__ p, const float* __restrict__ bias,
                float* __restrict__ out)
{
    const size_t i = ((size_t)blockIdx.x * 256 + threadIdx.x) * 4;
    float4 a = *(const float4*)(p + i);
    float4 b = *(const float4*)(p + 2097152 + i);
    const int col = (int)(i & 255);
    float4 o;
    o.x = a.x + b.x + bias[col + 0];
    o.y = a.y + b.y + bias[col + 1];
    o.z = a.z + b.z + bias[col + 2];
    o.w = a.w + b.w + bias[col + 3];
    *(float4*)(out + i) = o;
}

// ------------------------- fused flash attention (1-term fp16) -----------
// grid (16 Q-tiles, 32 b*h). 256 threads, Q-tile 128 rows persistent (64KB).
// K = raw k [tok, 256] fp16; V = per-batch vT [256 d, 2048 tok] fp16.
// FIXED-max softmax (only delta vs round-11): logits O(1), exp2 safe.
__global__ __launch_bounds__(256, 1)
void flash_attn(const f16* __restrict__ Qm_, const f16* __restrict__ K_,
                const f16* __restrict__ Vt_,
                f16* __restrict__ Oh_, f16* __restrict__ Ol_)
{
    extern __shared__ char smraw[];
    const uint32_t base = (smem_u32(smraw) + 1023) & ~1023u;
    const uint32_t sQ = base;               // 64KB
    const uint32_t sK = base + 65536;       // 2 bufs x 16KB
    const uint32_t sV = base + 98304;       // 2 subs x 16KB

    const int tid = threadIdx.x, lane = tid & 31, warp = tid >> 5;
    const int qr0 = blockIdx.x * 128;
    const int b = blockIdx.y >> 3, h = blockIdx.y & 7;
    const int wr = warp * 16;

    const f16* Qg = Qm_ + ((size_t)(b * 2048 + qr0)) * 2048 + h * 256;
    const f16* Kg = K_ + (size_t)b * 2048 * 256;
    const f16* Vg = Vt_ + (size_t)b * 256 * 2048;

    // ---- persistent Q load: 128 rows x 256 fp16 (512B rows), group 0 ----
#pragma unroll
    for (int i = 0; i < 16; i++) {
        int u = i * 256 + tid;
        int row = u >> 5, cu = u & 31;
        cpasync16(sQ + q_off(row, (uint32_t)cu << 4), Qg + (size_t)row * 2048 + cu * 8);
    }
    cp_commit();

    float O[32][4];
#pragma unroll
    for (int nd = 0; nd < 32; nd++)
#pragma unroll
        for (int r = 0; r < 4; r++) O[nd][r] = 0.0f;
    float sm0 = 0.0f, sm1 = 0.0f;

    // K chunk: [64 keys x 128 els] fp16 = 16KB; raw k row stride 256
    auto issueK = [&](int j, int c, int buf) {
        const uint32_t kb = sK + buf * 16384;
#pragma unroll
        for (int i = 0; i < 4; i++) {
            int u = i * 256 + tid;
            int row = u >> 4, cu = u & 15;
            cpasync16(kb + koff2(row, (uint32_t)cu << 4),
                      Kg + (size_t)(j * 64 + row) * 256 + c * 128 + cu * 8);
        }
        cp_commit();
    };
    // V sub: [256 d x 32 tok] fp16 = 16KB; vT row stride 2048
    auto issueV = [&](int j, int sub) {
        const uint32_t vb = sV + sub * 16384;
        const size_t keyc = (size_t)(j * 64 + sub * 32);
#pragma unroll
        for (int i = 0; i < 4; i++) {
            int u = i * 256 + tid;
            int row = u >> 2, cu = u & 3;
            cpasync16(vb + tile_off(row, cu * 16),
                      Vg + (size_t)row * 2048 + keyc + cu * 8);
        }
        cp_commit();
    };

    issueK(0, 0, 0);

    for (int j = 0; j < 32; j++) {
        float S[8][4];
#pragma unroll
        for (int ni = 0; ni < 8; ni++)
#pragma unroll
            for (int r = 0; r < 4; r++) S[ni][r] = 0.0f;

        // ---------------- QK^T: 2 chunks of 128 els ----------------
#pragma unroll
        for (int c = 0; c < 2; c++) {
            if (c == 0) { issueK(j, 1, 1); cp_wait1(); }
            else        { issueV(j, 0); issueV(j, 1); cp_wait2(); }
            __syncthreads();

            const uint32_t kbb = sK + c * 16384;
#pragma unroll
            for (int ks = 0; ks < 8; ks++) {
                const uint32_t cb = (uint32_t)(ks * 32 + ((lane >> 4) << 4));
                uint32_t ah[4];
                ldsm4(ah, sQ + q_off(wr + (lane & 15), (uint32_t)(c * 256) + cb));
#pragma unroll
                for (int t16 = 0; t16 < 4; t16++) {
                    uint32_t bh[4];
                    ldsm4(bh, kbb + koff2(t16 * 16 + (lane & 15), cb));
                    mma16816(S[t16 * 2 + 0], ah, bh[0], bh[2]);
                    mma16816(S[t16 * 2 + 1], ah, bh[1], bh[3]);
                }
            }
        }

        // ---------------- fixed-max softmax: P = exp2(S) -------------
        uint32_t Ph[4][4];
        float bs0 = 0.0f, bs1 = 0.0f;
#pragma unroll
        for (int ni = 0; ni < 8; ni++) {
            const float p0 = ex2(S[ni][0]), p1 = ex2(S[ni][1]);
            const float p2 = ex2(S[ni][2]), p3 = ex2(S[ni][3]);
            bs0 += p0 + p1; bs1 += p2 + p3;
            const int kk = ni >> 1, a2 = (ni & 1) << 1;
            Ph[kk][a2 + 0] = pack_f16x2(p0, p1);
            Ph[kk][a2 + 1] = pack_f16x2(p2, p3);
        }
        sm0 += bs0; sm1 += bs1;

        // ---------------- PV: O += P @ V ----------------
#pragma unroll
        for (int sub = 0; sub < 2; sub++) {
            if (sub == 0) {
                if (j + 1 < 32) { issueK(j + 1, 0, 0); cp_wait2(); }
                else cp_wait1();
            } else {
                if (j + 1 < 32) cp_wait1(); else cp_wait0();
            }
            __syncthreads();

            const uint32_t vb = sV + sub * 16384;
#pragma unroll
            for (int ks = 0; ks < 2; ks++) {
                const int kk = sub * 2 + ks;
                const uint32_t cb = (uint32_t)(ks * 32 + ((lane >> 4) << 4));
#pragma unroll
                for (int t16 = 0; t16 < 16; t16++) {
                    uint32_t vh[4];
                    ldsm4(vh, vb + tile_off(t16 * 16 + (lane & 15), cb));
                    mma16816(O[t16 * 2 + 0], Ph[kk], vh[0], vh[2]);
                    mma16816(O[t16 * 2 + 1], Ph[kk], vh[1], vh[3]);
                }
            }
        }
    }

    // ---------------- epilogue: normalize, write Pv hi/lo fp16 -----------
    sm0 += __shfl_xor_sync(0xFFFFFFFFu, sm0, 1);
    sm0 += __shfl_xor_sync(0xFFFFFFFFu, sm0, 2);
    sm1 += __shfl_xor_sync(0xFFFFFFFFu, sm1, 1);
    sm1 += __shfl_xor_sync(0xFFFFFFFFu, sm1, 2);
    const float inv0 = 1.0f / sm0, inv1 = 1.0f / sm1;

    const int r = lane >> 2, cq = (lane & 3) * 2;
    const size_t orow0 = ((size_t)(b * 2048 + qr0 + wr + r)) * 2048 + h * 256;
    const size_t orow1 = orow0 + 8 * 2048;
#pragma unroll
    for (int nd = 0; nd < 32; nd++) {
        const int col = nd * 8 + cq;
        const float v0 = O[nd][0] * inv0, v1 = O[nd][1] * inv0;
        const float v2 = O[nd][2] * inv1, v3 = O[nd][3] * inv1;
        f16 h0 = __float2half_rn(v0), h1 = __float2half_rn(v1);
        f16 h2 = __float2half_rn(v2), h3 = __float2half_rn(v3);
        *(__half2*)(Oh_ + orow0 + col) = __halves2half2(h0, h1);
        *(__half2*)(Ol_ + orow0 + col) = __halves2half2(
            __float2half_rn(v0 - __half2float(h0)),
            __float2half_rn(v1 - __half2float(h1)));
        *(__half2*)(Oh_ + orow1 + col) = __halves2half2(h2, h3);
        *(__half2*)(Ol_ + orow1 + col) = __halves2half2(
            __float2half_rn(v2 - __half2float(h2)),
            __float2half_rn(v3 - __half2float(h3)));
    }
}

// ------------------------- launcher --------------------------------------
extern "C" void kernel_launch(void* const* d_in, const int* in_sizes, int n_in,
                              void* d_out, int out_size)
{
    const float* q  = (const float*)d_in[0];
    const float* k  = (const float*)d_in[1];
    const float* v  = (const float*)d_in[2];
    const float* Wq = (const float*)d_in[3];
    const float* Wk = (const float*)d_in[4];
    const float* Wv = (const float*)d_in[5];
    const float* Wu = (const float*)d_in[6];
    const float* bu = (const float*)d_in[7];
    float* out = (float*)d_out;

#define SYM(p, s) void* p##_; cudaGetSymbolAddress(&p##_, s); auto* p = (decltype(&s[0]))p##_
    SYM(qh, g_qh); SYM(kh, g_kh);
    SYM(Wqh, g_Wqh); SYM(Wql, g_Wql);
    SYM(Wkh, g_Wkh); SYM(Wkl, g_Wkl);
    SYM(Wvh, g_Wvh); SYM(Wvl, g_Wvl);
    SYM(WuTh, g_WuTh); SYM(WuTl, g_WuTl);
    SYM(MT, g_MT); SYM(NTh, g_NTh); SYM(NTl, g_NTl);
    SYM(vT, g_vT); SYM(Qm, g_Qm);
    SYM(Oh, g_Oh); SYM(Ol, g_Ol);
    SYM(Part, g_Part);
#undef SYM

    const int SMEM1 = 3 * 16384 + 1024;     // 1-term: 3 bufs x 16KB
    const int SMEM3 = 3 * 32768 + 1024;     // 3-term: 3 bufs x 32KB
    cudaFuncSetAttribute(bgemm_mma<3, 1>, cudaFuncAttributeMaxDynamicSharedMemorySize, SMEM1);
    cudaFuncSetAttribute(bgemm_mma<3, 3>, cudaFuncAttributeMaxDynamicSharedMemorySize, SMEM3);
    cudaFuncSetAttribute(bgemm_mma<2, 3>, cudaFuncAttributeMaxDynamicSharedMemorySize, SMEM3);
    cudaFuncSetAttribute(bgemm_mma<0, 3>, cudaFuncAttributeMaxDynamicSharedMemorySize, SMEM3);
    const int FSMEM = 131072 + 1024;        // Q 64K + K 32K + V 32K
    cudaFuncSetAttribute(flash_attn, cudaFuncAttributeMaxDynamicSharedMemorySize, FSMEM);

    // fold softmax scale (1/16) and log2(e) into the Q projection
    const float alpha_q = 0.0625f * 1.44269504088896340736f;

    // 1. q,k -> fp16 (one launch)
    convert2<<<dim3(1024, 1, 2), 256>>>(q, k, qh, kh);

    // 2. Wq/Wk/Wv -> hi/lo fp16 planes (no transpose); Wu -> transposed hi/lo
    convhl3<<<dim3(256, 1, 3), 256>>>(Wq, Wk, Wv,
        Wqh, Wql, Wkh, Wkl, Wvh, Wvl);
    transpose_hilo<<<dim3(8, 64, 1), 256>>>(Wu, WuTh, WuTl, 2048, 256);

    // 3. v -> per-batch transposed fp16 vT [256 d, 2048 tok]
    transpose_vf16<<<dim3(8, 64, 4), 256>>>(v, vT);

    // 4. M^T[h*256+j][i] = sum_d Wk[j][h*256+d] Wq[i][h*256+d]  (3-term)
    bgemm_mma<3, 3><<<dim3(2, 2, 8), 256, SMEM3>>>(256,
        Wkh, Wkl, 2048, Wqh, Wql, 2048, nullptr, MT, nullptr, 256, 1.0f,
        256, 256L * 256);

    // 5. N^T[j][h*256+i] = sum_d WuT[j][h*256+d] Wv[i][h*256+d]  (3-term, hi/lo out)
    bgemm_mma<2, 3><<<dim3(2, 2, 8), 256, SMEM3>>>(256,
        WuTh, WuTl, 2048, Wvh, Wvl, 2048, nullptr, NTh, NTl, 2048, 1.0f,
        256, 256);

    // 6. Qm = q @ M (pre-scaled): [8192,2048] = [8192,256] @ [2048,256]^T
    bgemm_mma<3, 1><<<dim3(16, 64, 1), 256, SMEM1>>>(256,
        qh, nullptr, 256, MT, nullptr, 256, nullptr, Qm, nullptr, 2048, alpha_q,
        0, 0);

    // 7. fused attention vs raw k / vT; writes Pv hi/lo
    flash_attn<<<dim3(16, 32), 256, FSMEM>>>(Qm, kh, vT, Oh, Ol);

    // 8. out-projection, split-K=2: partials = Pv @ N  (3-term hi/lo)
    bgemm_mma<0, 3><<<dim3(2, 64, 2), 256, SMEM3>>>(1024,
        Oh, Ol, 2048, NTh, NTl, 2048, Part, nullptr, nullptr, 256, 1.0f,
        1024, 8192L * 256);

    // 9. out = part0 + part1 + bu
    reduce_add<<<2048, 256>>>(Part, bu, out);
}

// round 14
// speedup vs baseline: 1.1881x; 1.1881x over previous
#include <cuda_runtime.h>
#include <cuda_fp16.h>
#include <math.h>
#include <stdint.h>

// B=4, M=N=2048, D_QK=D_V=256, H=8.  All fp32 in/out.
// Weight-composed fp16 pipeline (round-11 structure):
//   S  = q (Wq_h Wk_h^T) k^T  -> precompute M^T, Qm = q@M, flash vs raw k
//   out = sum_h (P v) (Wv_h Wu_h) -> precompute N^T hi/lo, flash PV vs raw v,
//         out-projection = Pv @ N (3-term hi/lo, split-K=2)
// Flash delta vs round-11: K/V staged as FULL 64x256 / 256x64 blocks,
// double-buffered; 2 barriers per j-block (was 4). Online softmax kept.

typedef __half f16;

// ------------------------- scratch (static, no allocation) ---------------
__device__ f16 g_qh[8192L*256], g_kh[8192L*256];
__device__ f16 g_Wqh[256L*2048], g_Wql[256L*2048];
__device__ f16 g_Wkh[256L*2048], g_Wkl[256L*2048];
__device__ f16 g_Wvh[256L*2048], g_Wvl[256L*2048];
__device__ f16 g_WuTh[256L*2048], g_WuTl[256L*2048];
__device__ f16 g_MT[2048L*256];                    // (Wq_h Wk_h^T)^T stacked
__device__ f16 g_NTh[256L*2048], g_NTl[256L*2048]; // (Wv_h Wu_h)^T stacked
__device__ f16 g_vT[4L*256*2048];                  // per-batch v^T [256 d][2048 tok]
__device__ f16 g_Qm[8192L*2048];
__device__ f16 g_Oh[8192L*2048], g_Ol[8192L*2048];
__device__ float g_Part[2L*8192*256];              // split-K partials

// ------------------------- helpers ---------------------------------------
__device__ __forceinline__ uint32_t smem_u32(const void* p) {
    uint32_t a;
    asm("{ .reg .u64 t; cvta.to.shared.u64 t, %1; cvt.u32.u64 %0, t; }" : "=r"(a) : "l"(p));
    return a;
}
__device__ __forceinline__ void cpasync16(uint32_t s, const void* g) {
    asm volatile("cp.async.cg.shared.global [%0], [%1], 16;" :: "r"(s), "l"(g) : "memory");
}
__device__ __forceinline__ void cp_commit() {
    asm volatile("cp.async.commit_group;" ::: "memory");
}
__device__ __forceinline__ void cp_wait0() { asm volatile("cp.async.wait_group 0;" ::: "memory"); }
__device__ __forceinline__ void cp_wait1() { asm volatile("cp.async.wait_group 1;" ::: "memory"); }
__device__ __forceinline__ void cp_wait2() { asm volatile("cp.async.wait_group 2;" ::: "memory"); }
__device__ __forceinline__ void ldsm4(uint32_t* r, uint32_t addr) {
    asm volatile("ldmatrix.sync.aligned.m8n8.x4.shared.b16 {%0,%1,%2,%3}, [%4];"
                 : "=r"(r[0]), "=r"(r[1]), "=r"(r[2]), "=r"(r[3]) : "r"(addr));
}
__device__ __forceinline__ void mma16816(float* d, const uint32_t* a,
                                         uint32_t b0, uint32_t b1) {
    asm volatile("mma.sync.aligned.m16n8k16.row.col.f32.f16.f16.f32 "
                 "{%0,%1,%2,%3}, {%4,%5,%6,%7}, {%8,%9}, {%0,%1,%2,%3};"
                 : "+f"(d[0]), "+f"(d[1]), "+f"(d[2]), "+f"(d[3])
                 : "r"(a[0]), "r"(a[1]), "r"(a[2]), "r"(a[3]), "r"(b0), "r"(b1));
}
__device__ __forceinline__ float ex2(float x) {
    float r;
    asm("ex2.approx.f32 %0, %1;" : "=f"(r) : "f"(x));
    return r;
}
__device__ __forceinline__ uint32_t pack_f16x2(float lo, float hi) {
    uint32_t r;
    asm("cvt.rn.f16x2.f32 %0, %1, %2;" : "=r"(r) : "f"(hi), "f"(lo));
    return r;
}
// tile layout: rows x 64B; two rows per 128B line + SW128 xor.
__device__ __forceinline__ uint32_t tile_off(int row, int kb) {
    uint32_t o = ((uint32_t)(row >> 1) << 7) | ((uint32_t)(row & 1) << 6) | (uint32_t)kb;
    return o ^ ((o >> 3) & 0x70);
}
// 512B-row tile (persistent Q and full-K blocks)
__device__ __forceinline__ uint32_t q_off(int row, uint32_t colb) {
    return (uint32_t)row * 512 + (colb ^ ((uint32_t)(row & 7) << 4));
}
// 128B-row tile (full-V blocks: 64 tok * 2B per row)
__device__ __forceinline__ uint32_t v_off(int row, uint32_t colb) {
    return (uint32_t)row * 128 + (colb ^ ((uint32_t)(row & 7) << 4));
}
__device__ __forceinline__ void split_store16(float v, f16* ph, f16* pl) {
    f16 h = __float2half_rn(v);
    *ph = h;
    *pl = __float2half_rn(v - __half2float(h));
}

// ------------------------- convert fp32 -> fp16 (q,k fused) --------------
__global__ __launch_bounds__(256)
void convert2(const float* __restrict__ x0, const float* __restrict__ x1,
              f16* __restrict__ h0, f16* __restrict__ h1)
{
    const int z = blockIdx.z;
    const float* x = (z == 0) ? x0 : x1;
    f16* h = (z == 0) ? h0 : h1;
    size_t base = ((size_t)blockIdx.x * 256 + threadIdx.x) * 8;
#pragma unroll
    for (int j = 0; j < 8; j++)
        h[base + j] = __float2half_rn(x[base + j]);
}

// three fp32 tensors -> hi/lo fp16 planes, no transpose (Wq, Wk, Wv)
__global__ __launch_bounds__(256)
void convhl3(const float* __restrict__ w0, const float* __restrict__ w1,
             const float* __restrict__ w2,
             f16* __restrict__ h0, f16* __restrict__ l0,
             f16* __restrict__ h1, f16* __restrict__ l1,
             f16* __restrict__ h2, f16* __restrict__ l2)
{
    const int z = blockIdx.z;
    const float* x = (z == 0) ? w0 : (z == 1) ? w1 : w2;
    f16* h = (z == 0) ? h0 : (z == 1) ? h1 : h2;
    f16* l = (z == 0) ? l0 : (z == 1) ? l1 : l2;
    size_t base = ((size_t)blockIdx.x * 256 + threadIdx.x) * 8;
#pragma unroll
    for (int j = 0; j < 8; j++)
        split_store16(x[base + j], h + base + j, l + base + j);
}

// Wu transpose -> hi/lo fp16 planes
__global__ __launch_bounds__(256)
void transpose_hilo(const float* __restrict__ in, f16* __restrict__ oh,
                    f16* __restrict__ ol, int R, int C)
{
    __shared__ float t[32][33];
    int c0 = blockIdx.x * 32, r0 = blockIdx.y * 32;
    int x = threadIdx.x & 31, y = (threadIdx.x >> 5) * 4;
#pragma unroll
    for (int i = 0; i < 4; i++)
        t[y + i][x] = in[(size_t)(r0 + y + i) * C + c0 + x];
    __syncthreads();
#pragma unroll
    for (int i = 0; i < 4; i++) {
        size_t o = (size_t)(c0 + y + i) * R + r0 + x;
        split_store16(t[x][y + i], oh + o, ol + o);
    }
}

// per-batch transpose: v fp32 [2048 tok, 256 d] -> vT fp16 [256 d, 2048 tok]
__global__ __launch_bounds__(256)
void transpose_vf16(const float* __restrict__ in, f16* __restrict__ out)
{
    __shared__ float t[32][33];
    const size_t ioff = (size_t)blockIdx.z * 2048 * 256;
    const size_t ooff = (size_t)blockIdx.z * 256 * 2048;
    int c0 = blockIdx.x * 32;   // d block
    int r0 = blockIdx.y * 32;   // tok block
    int x = threadIdx.x & 31, y = (threadIdx.x >> 5) * 4;
#pragma unroll
    for (int i = 0; i < 4; i++)
        t[y + i][x] = in[ioff + (size_t)(r0 + y + i) * 256 + c0 + x];
    __syncthreads();
#pragma unroll
    for (int i = 0; i < 4; i++)
        out[ooff + (size_t)(c0 + y + i) * 2048 + r0 + x] =
            __float2half_rn(t[x][y + i]);
}

// ------------------------- mma.sync batched GEMM -------------------------
// C[M,N] = alpha * A[M,K] @ B[N,K]^T, fp16 K-major operands.
// TERMS: 1 = Ah*Bh; 3 = + Ah*Bl + Al*Bh.
// OUTMODE: 0 = f32 (Cf), 2 = hi/lo fp16 (Ch,Cl), 3 = hi fp16 (Ch).
// blockIdx.z: A/B element offset z*kzoff, output element offset z*czoff.
template<int OUTMODE, int TERMS>
__global__ __launch_bounds__(256)
void bgemm_mma(int K,
               const f16* __restrict__ Ah, const f16* __restrict__ Al, int lda,
               const f16* __restrict__ Bh, const f16* __restrict__ Bl, int ldb,
               float* __restrict__ Cf, f16* __restrict__ Ch, f16* __restrict__ Cl,
               int ldc, float alpha, long kzoff, long czoff)
{
    extern __shared__ char smem_raw[];
    const uint32_t base = (smem_u32(smem_raw) + 1023) & ~1023u;
    constexpr uint32_t BUF = (TERMS == 3) ? 32768 : 16384;
    constexpr uint32_t OFF_B = (TERMS == 3) ? 16384 : 8192;

    const long kz = (long)blockIdx.z * kzoff;
    Ah += kz; Bh += kz;
    if (TERMS == 3) { Al += kz; Bl += kz; }
    const long cz = (long)blockIdx.z * czoff;
    if (OUTMODE == 0) Cf += cz;
    else { Ch += cz; if (OUTMODE == 2) Cl += cz; }

    const int tid  = threadIdx.x;
    const int lane = tid & 31;
    const int warp = tid >> 5;
    const int brow = blockIdx.y * 128;
    const int bcol = blockIdx.x * 128;
    const int wr   = (warp >> 2) * 64;
    const int wc   = (warp & 3) * 32;

    const int r0u = (tid * 2) >> 2,      j0u = (tid * 2) & 3;
    const int r1u = (tid * 2 + 1) >> 2,  j1u = (tid * 2 + 1) & 3;

    float acc[4][4][4];
#pragma unroll
    for (int mi = 0; mi < 4; mi++)
#pragma unroll
        for (int ni = 0; ni < 4; ni++)
#pragma unroll
            for (int r = 0; r < 4; r++) acc[mi][ni][r] = 0.0f;

    const int nchunk = K >> 5;

    auto issue = [&](int c, int buf) {
        const int k0 = c << 5;
        const uint32_t sb = base + buf * BUF;
        const uint32_t s0 = tile_off(r0u, j0u * 16);
        const uint32_t s1 = tile_off(r1u, j1u * 16);
        const size_t ga0 = (size_t)(brow + r0u) * lda + k0 + j0u * 8;
        const size_t ga1 = (size_t)(brow + r1u) * lda + k0 + j1u * 8;
        const size_t gb0 = (size_t)(bcol + r0u) * ldb + k0 + j0u * 8;
        const size_t gb1 = (size_t)(bcol + r1u) * ldb + k0 + j1u * 8;
        cpasync16(sb + s0, Ah + ga0);
        cpasync16(sb + s1, Ah + ga1);
        cpasync16(sb + OFF_B + s0, Bh + gb0);
        cpasync16(sb + OFF_B + s1, Bh + gb1);
        if (TERMS == 3) {
            cpasync16(sb +  8192 + s0, Al + ga0);
            cpasync16(sb +  8192 + s1, Al + ga1);
            cpasync16(sb + 24576 + s0, Bl + gb0);
            cpasync16(sb + 24576 + s1, Bl + gb1);
        }
        cp_commit();
    };

    issue(0, 0);
    issue(1, 1);

    int bufc = 0;
    for (int c = 0; c < nchunk; c++) {
        if (c + 1 < nchunk) cp_wait1(); else cp_wait0();
        __syncthreads();
        if (c + 2 < nchunk) {
            int nb = bufc + 2; if (nb >= 3) nb -= 3;
            issue(c + 2, nb);
        }

        const uint32_t sb = base + bufc * BUF;
#pragma unroll
        for (int ks = 0; ks < 2; ks++) {
            const int kb = ks * 32 + (lane >> 4) * 16;
            uint32_t bh[2][4], bl[2][4];
#pragma unroll
            for (int t16 = 0; t16 < 2; t16++) {
                const uint32_t so = tile_off(wc + t16 * 16 + (lane & 15), kb);
                ldsm4(bh[t16], sb + OFF_B + so);
                if (TERMS == 3) ldsm4(bl[t16], sb + 24576 + so);
            }
#pragma unroll
            for (int mi = 0; mi < 4; mi++) {
                uint32_t ah[4], al[4];
                const uint32_t so = tile_off(wr + mi * 16 + (lane & 15), kb);
                ldsm4(ah, sb + so);
                if (TERMS == 3) ldsm4(al, sb + 8192 + so);
#pragma unroll
                for (int ni = 0; ni < 4; ni++) {
                    const int t16 = ni >> 1, sub = ni & 1;
                    const uint32_t bh0 = bh[t16][sub], bh1 = bh[t16][2 + sub];
                    mma16816(acc[mi][ni], ah, bh0, bh1);
                    if (TERMS == 3) {
                        const uint32_t bl0 = bl[t16][sub], bl1 = bl[t16][2 + sub];
                        mma16816(acc[mi][ni], ah, bl0, bl1);
                        mma16816(acc[mi][ni], al, bh0, bh1);
                    }
                }
            }
        }
        if (++bufc == 3) bufc = 0;
    }

#pragma unroll
    for (int mi = 0; mi < 4; mi++) {
#pragma unroll
        for (int half = 0; half < 2; half++) {
            const int row = brow + wr + mi * 16 + (lane >> 2) + half * 8;
#pragma unroll
            for (int ni = 0; ni < 4; ni++) {
                const int col = bcol + wc + ni * 8 + (lane & 3) * 2;
                float v0 = acc[mi][ni][half * 2 + 0] * alpha;
                float v1 = acc[mi][ni][half * 2 + 1] * alpha;
                if (OUTMODE == 0) {
                    float2 o; o.x = v0; o.y = v1;
                    *(float2*)(Cf + (size_t)row * ldc + col) = o;
                } else if (OUTMODE == 3) {
                    *(uint32_t*)(Ch + (size_t)row * ldc + col) = pack_f16x2(v0, v1);
                } else {
                    const size_t off = (size_t)row * ldc + col;
                    f16 h0 = __float2half_rn(v0), h1 = __float2half_rn(v1);
                    *(__half2*)(Ch + off) = __halves2half2(h0, h1);
                    *(__half2*)(Cl + off) = __halves2half2(
                        __float2half_rn(v0 - __half2float(h0)),
                        __float2half_rn(v1 - __half2float(h1)));
                }
            }
        }
    }
}

// ------------------------- split-K reduce + bias -------------------------
__global__ __launch_bounds__(256)
void reduce_add(const float* __restrict__ p, const float* __restrict__ bias,
                float* __restrict__ out)
{
    const size_t i = ((size_t)blockIdx.x * 256 + threadIdx.x) * 4;
    float4 a = *(const float4*)(p + i);
    float4 b = *(const float4*)(p + 2097152 + i);
    const int col = (int)(i & 255);
    float4 o;
    o.x = a.x + b.x + bias[col + 0];
    o.y = a.y + b.y + bias[col + 1];
    o.z = a.z + b.z + bias[col + 2];
    o.w = a.w + b.w + bias[col + 3];
    *(float4*)(out + i) = o;
}

// ------------------------- fused flash attention (1-term fp16) -----------
// grid (16 Q-tiles, 32 b*h). 256 threads, Q-tile 128 rows persistent (64KB).
// K staged as full [64 keys x 256 els] blocks (2 bufs x 32KB, 512B rows),
// V as full [256 d x 64 tok] blocks (2 bufs x 32KB, 128B rows).
// 2 barriers per j-block. Online softmax (round-11 form).
__global__ __launch_bounds__(256, 1)
void flash_attn(const f16* __restrict__ Qm_, const f16* __restrict__ K_,
                const f16* __restrict__ Vt_,
                f16* __restrict__ Oh_, f16* __restrict__ Ol_)
{
    extern __shared__ char smraw[];
    const uint32_t base = (smem_u32(smraw) + 1023) & ~1023u;
    const uint32_t sQ = base;               // 64KB
    const uint32_t sK = base + 65536;       // 2 bufs x 32KB
    const uint32_t sV = base + 131072;      // 2 bufs x 32KB

    const int tid = threadIdx.x, lane = tid & 31, warp = tid >> 5;
    const int qr0 = blockIdx.x * 128;
    const int b = blockIdx.y >> 3, h = blockIdx.y & 7;
    const int wr = warp * 16;

    const f16* Qg = Qm_ + ((size_t)(b * 2048 + qr0)) * 2048 + h * 256;
    const f16* Kg = K_ + (size_t)b * 2048 * 256;
    const f16* Vg = Vt_ + (size_t)b * 256 * 2048;

    // ---- persistent Q load: 128 rows x 256 fp16 (512B rows), group 0 ----
#pragma unroll
    for (int i = 0; i < 16; i++) {
        int u = i * 256 + tid;
        int row = u >> 5, cu = u & 31;
        cpasync16(sQ + q_off(row, (uint32_t)cu << 4), Qg + (size_t)row * 2048 + cu * 8);
    }
    cp_commit();

    float O[32][4];
#pragma unroll
    for (int nd = 0; nd < 32; nd++)
#pragma unroll
        for (int r = 0; r < 4; r++) O[nd][r] = 0.0f;
    float m2_0 = -1e30f, m2_1 = -1e30f;
    float sm0 = 0.0f, sm1 = 0.0f;

    // K block: [64 keys x 256 els] = 32KB; 2048 units, 8/thread
    auto issueK = [&](int j, int buf) {
        const uint32_t kb = sK + buf * 32768;
#pragma unroll
        for (int i = 0; i < 8; i++) {
            int u = i * 256 + tid;
            int row = u >> 5, cu = u & 31;
            cpasync16(kb + q_off(row, (uint32_t)cu << 4),
                      Kg + (size_t)(j * 64 + row) * 256 + cu * 8);
        }
        cp_commit();
    };
    // V block: [256 d x 64 tok] = 32KB (128B rows); 2048 units, 8/thread
    auto issueV = [&](int j, int buf) {
        const uint32_t vb = sV + buf * 32768;
#pragma unroll
        for (int i = 0; i < 8; i++) {
            int u = i * 256 + tid;
            int row = u >> 3, cu = u & 7;
            cpasync16(vb + v_off(row, (uint32_t)cu << 4),
                      Vg + (size_t)row * 2048 + j * 64 + cu * 8);
        }
        cp_commit();
    };

    issueK(0, 0);
    issueV(0, 0);
    issueK(1, 1);

    for (int j = 0; j < 32; j++) {
        float S[8][4];
#pragma unroll
        for (int ni = 0; ni < 8; ni++)
#pragma unroll
            for (int r = 0; r < 4; r++) S[ni][r] = 0.0f;

        // ---------------- QK^T: full 256 els, one phase ----------------
        if (j < 31) cp_wait2(); else cp_wait1();
        __syncthreads();
        if (j + 1 < 32) issueV(j + 1, (j + 1) & 1);

        {
            const uint32_t kbb = sK + (j & 1) * 32768;
#pragma unroll
            for (int ks = 0; ks < 16; ks++) {
                const uint32_t cb = (uint32_t)(ks * 32 + ((lane >> 4) << 4));
                uint32_t ah[4];
                ldsm4(ah, sQ + q_off(wr + (lane & 15), cb));
#pragma unroll
                for (int t16 = 0; t16 < 4; t16++) {
                    uint32_t bh[4];
                    ldsm4(bh, kbb + q_off(t16 * 16 + (lane & 15), cb));
                    mma16816(S[t16 * 2 + 0], ah, bh[0], bh[2]);
                    mma16816(S[t16 * 2 + 1], ah, bh[1], bh[3]);
                }
            }
        }

        // ---------------- online softmax (warp-local, round-11) ------
        float rx0 = -1e30f, rx1 = -1e30f;
#pragma unroll
        for (int ni = 0; ni < 8; ni++) {
            rx0 = fmaxf(rx0, fmaxf(S[ni][0], S[ni][1]));
            rx1 = fmaxf(rx1, fmaxf(S[ni][2], S[ni][3]));
        }
        rx0 = fmaxf(rx0, __shfl_xor_sync(0xFFFFFFFFu, rx0, 1));
        rx0 = fmaxf(rx0, __shfl_xor_sync(0xFFFFFFFFu, rx0, 2));
        rx1 = fmaxf(rx1, __shfl_xor_sync(0xFFFFFFFFu, rx1, 1));
        rx1 = fmaxf(rx1, __shfl_xor_sync(0xFFFFFFFFu, rx1, 2));
        const float mn0 = fmaxf(m2_0, rx0), mn1 = fmaxf(m2_1, rx1);
        const float sc0 = ex2(m2_0 - mn0), sc1 = ex2(m2_1 - mn1);
        m2_0 = mn0; m2_1 = mn1;
        if (!__all_sync(0xFFFFFFFFu, (sc0 == 1.0f) && (sc1 == 1.0f))) {
#pragma unroll
            for (int nd = 0; nd < 32; nd++) {
                O[nd][0] *= sc0; O[nd][1] *= sc0;
                O[nd][2] *= sc1; O[nd][3] *= sc1;
            }
        }
        sm0 *= sc0; sm1 *= sc1;

        uint32_t Ph[4][4];
        float bs0 = 0.0f, bs1 = 0.0f;
#pragma unroll
        for (int ni = 0; ni < 8; ni++) {
            const float p0 = ex2(S[ni][0] - mn0), p1 = ex2(S[ni][1] - mn0);
            const float p2 = ex2(S[ni][2] - mn1), p3 = ex2(S[ni][3] - mn1);
            bs0 += p0 + p1; bs1 += p2 + p3;
            const int kk = ni >> 1, a2 = (ni & 1) << 1;
            Ph[kk][a2 + 0] = pack_f16x2(p0, p1);
            Ph[kk][a2 + 1] = pack_f16x2(p2, p3);
        }
        sm0 += bs0; sm1 += bs1;

        // ---------------- PV: full 64 tok, one phase ----------------
        if (j < 31) cp_wait2(); else cp_wait0();
        __syncthreads();
        if (j + 2 < 32) issueK(j + 2, j & 1);

        {
            const uint32_t vb = sV + (j & 1) * 32768;
#pragma unroll
            for (int kk = 0; kk < 4; kk++) {
                const uint32_t cb = (uint32_t)(kk * 32 + ((lane >> 4) << 4));
#pragma unroll
                for (int t16 = 0; t16 < 16; t16++) {
                    uint32_t vh[4];
                    ldsm4(vh, vb + v_off(t16 * 16 + (lane & 15), cb));
                    mma16816(O[t16 * 2 + 0], Ph[kk], vh[0], vh[2]);
                    mma16816(O[t16 * 2 + 1], Ph[kk], vh[1], vh[3]);
                }
            }
        }
    }

    // ---------------- epilogue: normalize, write Pv hi/lo fp16 -----------
    sm0 += __shfl_xor_sync(0xFFFFFFFFu, sm0, 1);
    sm0 += __shfl_xor_sync(0xFFFFFFFFu, sm0, 2);
    sm1 += __shfl_xor_sync(0xFFFFFFFFu, sm1, 1);
    sm1 += __shfl_xor_sync(0xFFFFFFFFu, sm1, 2);
    const float inv0 = 1.0f / sm0, inv1 = 1.0f / sm1;

    const int r = lane >> 2, cq = (lane & 3) * 2;
    const size_t orow0 = ((size_t)(b * 2048 + qr0 + wr + r)) * 2048 + h * 256;
    const size_t orow1 = orow0 + 8 * 2048;
#pragma unroll
    for (int nd = 0; nd < 32; nd++) {
        const int col = nd * 8 + cq;
        const float v0 = O[nd][0] * inv0, v1 = O[nd][1] * inv0;
        const float v2 = O[nd][2] * inv1, v3 = O[nd][3] * inv1;
        f16 h0 = __float2half_rn(v0), h1 = __float2half_rn(v1);
        f16 h2 = __float2half_rn(v2), h3 = __float2half_rn(v3);
        *(__half2*)(Oh_ + orow0 + col) = __halves2half2(h0, h1);
        *(__half2*)(Ol_ + orow0 + col) = __halves2half2(
            __float2half_rn(v0 - __half2float(h0)),
            __float2half_rn(v1 - __half2float(h1)));
        *(__half2*)(Oh_ + orow1 + col) = __halves2half2(h2, h3);
        *(__half2*)(Ol_ + orow1 + col) = __halves2half2(
            __float2half_rn(v2 - __half2float(h2)),
            __float2half_rn(v3 - __half2float(h3)));
    }
}

// ------------------------- launcher --------------------------------------
extern "C" void kernel_launch(void* const* d_in, const int* in_sizes, int n_in,
                              void* d_out, int out_size)
{
    const float* q  = (const float*)d_in[0];
    const float* k  = (const float*)d_in[1];
    const float* v  = (const float*)d_in[2];
    const float* Wq = (const float*)d_in[3];
    const float* Wk = (const float*)d_in[4];
    const float* Wv = (const float*)d_in[5];
    const float* Wu = (const float*)d_in[6];
    const float* bu = (const float*)d_in[7];
    float* out = (float*)d_out;

#define SYM(p, s) void* p##_; cudaGetSymbolAddress(&p##_, s); auto* p = (decltype(&s[0]))p##_
    SYM(qh, g_qh); SYM(kh, g_kh);
    SYM(Wqh, g_Wqh); SYM(Wql, g_Wql);
    SYM(Wkh, g_Wkh); SYM(Wkl, g_Wkl);
    SYM(Wvh, g_Wvh); SYM(Wvl, g_Wvl);
    SYM(WuTh, g_WuTh); SYM(WuTl, g_WuTl);
    SYM(MT, g_MT); SYM(NTh, g_NTh); SYM(NTl, g_NTl);
    SYM(vT, g_vT); SYM(Qm, g_Qm);
    SYM(Oh, g_Oh); SYM(Ol, g_Ol);
    SYM(Part, g_Part);
#undef SYM

    const int SMEM1 = 3 * 16384 + 1024;     // 1-term: 3 bufs x 16KB
    const int SMEM3 = 3 * 32768 + 1024;     // 3-term: 3 bufs x 32KB
    cudaFuncSetAttribute(bgemm_mma<3, 1>, cudaFuncAttributeMaxDynamicSharedMemorySize, SMEM1);
    cudaFuncSetAttribute(bgemm_mma<3, 3>, cudaFuncAttributeMaxDynamicSharedMemorySize, SMEM3);
    cudaFuncSetAttribute(bgemm_mma<2, 3>, cudaFuncAttributeMaxDynamicSharedMemorySize, SMEM3);
    cudaFuncSetAttribute(bgemm_mma<0, 3>, cudaFuncAttributeMaxDynamicSharedMemorySize, SMEM3);
    const int FSMEM = 196608 + 1024;        // Q 64K + K 64K + V 64K
    cudaFuncSetAttribute(flash_attn, cudaFuncAttributeMaxDynamicSharedMemorySize, FSMEM);

    // fold softmax scale (1/16) and log2(e) into the Q projection
    const float alpha_q = 0.0625f * 1.44269504088896340736f;

    // 1. q,k -> fp16 (one launch)
    convert2<<<dim3(1024, 1, 2), 256>>>(q, k, qh, kh);

    // 2. Wq/Wk/Wv -> hi/lo fp16 planes (no transpose); Wu -> transposed hi/lo
    convhl3<<<dim3(256, 1, 3), 256>>>(Wq, Wk, Wv,
        Wqh, Wql, Wkh, Wkl, Wvh, Wvl);
    transpose_hilo<<<dim3(8, 64, 1), 256>>>(Wu, WuTh, WuTl, 2048, 256);

    // 3. v -> per-batch transposed fp16 vT [256 d, 2048 tok]
    transpose_vf16<<<dim3(8, 64, 4), 256>>>(v, vT);

    // 4. M^T[h*256+j][i] = sum_d Wk[j][h*256+d] Wq[i][h*256+d]  (3-term)
    bgemm_mma<3, 3><<<dim3(2, 2, 8), 256, SMEM3>>>(256,
        Wkh, Wkl, 2048, Wqh, Wql, 2048, nullptr, MT, nullptr, 256, 1.0f,
        256, 256L * 256);

    // 5. N^T[j][h*256+i] = sum_d WuT[j][h*256+d] Wv[i][h*256+d]  (3-term, hi/lo out)
    bgemm_mma<2, 3><<<dim3(2, 2, 8), 256, SMEM3>>>(256,
        WuTh, WuTl, 2048, Wvh, Wvl, 2048, nullptr, NTh, NTl, 2048, 1.0f,
        256, 256);

    // 6. Qm = q @ M (pre-scaled): [8192,2048] = [8192,256] @ [2048,256]^T
    bgemm_mma<3, 1><<<dim3(16, 64, 1), 256, SMEM1>>>(256,
        qh, nullptr, 256, MT, nullptr, 256, nullptr, Qm, nullptr, 2048, alpha_q,
        0, 0);

    // 7. fused attention vs raw k / vT; writes Pv hi/lo
    flash_attn<<<dim3(16, 32), 256, FSMEM>>>(Qm, kh, vT, Oh, Ol);

    // 8. out-projection, split-K=2: partials = Pv @ N  (3-term hi/lo)
    bgemm_mma<0, 3><<<dim3(2, 64, 2), 256, SMEM3>>>(1024,
        Oh, Ol, 2048, NTh, NTl, 2048, Part, nullptr, nullptr, 256, 1.0f,
        1024, 8192L * 256);

    // 9. out = part0 + part1 + bu
    reduce_add<<<2048, 256>>>(Part, bu, out);
}

// round 16
// speedup vs baseline: 1.2519x; 1.0537x over previous
#include <cuda_runtime.h>
#include <cuda_fp16.h>
#include <math.h>
#include <stdint.h>

// B=4, M=N=2048, D_QK=D_V=256, H=8.  All fp32 in/out.
// Weight-composed fp16 pipeline:
//   S  = q (Wq_h Wk_h^T) k^T  -> precompute M^T, Qm = q@M, flash vs raw k
//   out = sum_h (P v) (Wv_h Wu_h) -> precompute N^T hi/lo, flash PV vs raw v,
//         out-projection = Pv @ N (3-term hi/lo, split-K=2)
// Flash: full-block K/V phases, 2 barriers per j (round-14 winner).
// bgemm: 64-element chunks; staging fixed to 4 units/thread/plane (1024
// 16B-units per 128x64 tile -- the round-15 NaN was loading only half).

typedef __half f16;

// ------------------------- scratch (static, no allocation) ---------------
__device__ f16 g_qh[8192L*256], g_kh[8192L*256];
__device__ f16 g_Wqh[256L*2048], g_Wql[256L*2048];
__device__ f16 g_Wkh[256L*2048], g_Wkl[256L*2048];
__device__ f16 g_Wvh[256L*2048], g_Wvl[256L*2048];
__device__ f16 g_WuTh[256L*2048], g_WuTl[256L*2048];
__device__ f16 g_MT[2048L*256];                    // (Wq_h Wk_h^T)^T stacked
__device__ f16 g_NTh[256L*2048], g_NTl[256L*2048]; // (Wv_h Wu_h)^T stacked
__device__ f16 g_vT[4L*256*2048];                  // per-batch v^T [256 d][2048 tok]
__device__ f16 g_Qm[8192L*2048];
__device__ f16 g_Oh[8192L*2048], g_Ol[8192L*2048];
__device__ float g_Part[2L*8192*256];              // split-K partials

// ------------------------- helpers ---------------------------------------
__device__ __forceinline__ uint32_t smem_u32(const void* p) {
    uint32_t a;
    asm("{ .reg .u64 t; cvta.to.shared.u64 t, %1; cvt.u32.u64 %0, t; }" : "=r"(a) : "l"(p));
    return a;
}
__device__ __forceinline__ void cpasync16(uint32_t s, const void* g) {
    asm volatile("cp.async.cg.shared.global [%0], [%1], 16;" :: "r"(s), "l"(g) : "memory");
}
__device__ __forceinline__ void cp_commit() {
    asm volatile("cp.async.commit_group;" ::: "memory");
}
__device__ __forceinline__ void cp_wait0() { asm volatile("cp.async.wait_group 0;" ::: "memory"); }
__device__ __forceinline__ void cp_wait1() { asm volatile("cp.async.wait_group 1;" ::: "memory"); }
__device__ __forceinline__ void cp_wait2() { asm volatile("cp.async.wait_group 2;" ::: "memory"); }
__device__ __forceinline__ void ldsm4(uint32_t* r, uint32_t addr) {
    asm volatile("ldmatrix.sync.aligned.m8n8.x4.shared.b16 {%0,%1,%2,%3}, [%4];"
                 : "=r"(r[0]), "=r"(r[1]), "=r"(r[2]), "=r"(r[3]) : "r"(addr));
}
__device__ __forceinline__ void mma16816(float* d, const uint32_t* a,
                                         uint32_t b0, uint32_t b1) {
    asm volatile("mma.sync.aligned.m16n8k16.row.col.f32.f16.f16.f32 "
                 "{%0,%1,%2,%3}, {%4,%5,%6,%7}, {%8,%9}, {%0,%1,%2,%3};"
                 : "+f"(d[0]), "+f"(d[1]), "+f"(d[2]), "+f"(d[3])
                 : "r"(a[0]), "r"(a[1]), "r"(a[2]), "r"(a[3]), "r"(b0), "r"(b1));
}
__device__ __forceinline__ float ex2(float x) {
    float r;
    asm("ex2.approx.f32 %0, %1;" : "=f"(r) : "f"(x));
    return r;
}
__device__ __forceinline__ uint32_t pack_f16x2(float lo, float hi) {
    uint32_t r;
    asm("cvt.rn.f16x2.f32 %0, %1, %2;" : "=r"(r) : "f"(hi), "f"(lo));
    return r;
}
// 512B-row tile (persistent Q and full-K blocks)
__device__ __forceinline__ uint32_t q_off(int row, uint32_t colb) {
    return (uint32_t)row * 512 + (colb ^ ((uint32_t)(row & 7) << 4));
}
// 128B-row tile (full-V blocks and bgemm 64-el chunk tiles)
__device__ __forceinline__ uint32_t v_off(int row, uint32_t colb) {
    return (uint32_t)row * 128 + (colb ^ ((uint32_t)(row & 7) << 4));
}
__device__ __forceinline__ void split_store16(float v, f16* ph, f16* pl) {
    f16 h = __float2half_rn(v);
    *ph = h;
    *pl = __float2half_rn(v - __half2float(h));
}

// ------------------------- convert fp32 -> fp16 (q,k fused) --------------
__global__ __launch_bounds__(256)
void convert2(const float* __restrict__ x0, const float* __restrict__ x1,
              f16* __restrict__ h0, f16* __restrict__ h1)
{
    const int z = blockIdx.z;
    const float* x = (z == 0) ? x0 : x1;
    f16* h = (z == 0) ? h0 : h1;
    size_t base = ((size_t)blockIdx.x * 256 + threadIdx.x) * 8;
#pragma unroll
    for (int j = 0; j < 8; j++)
        h[base + j] = __float2half_rn(x[base + j]);
}

// three fp32 tensors -> hi/lo fp16 planes, no transpose (Wq, Wk, Wv)
__global__ __launch_bounds__(256)
void convhl3(const float* __restrict__ w0, const float* __restrict__ w1,
             const float* __restrict__ w2,
             f16* __restrict__ h0, f16* __restrict__ l0,
             f16* __restrict__ h1, f16* __restrict__ l1,
             f16* __restrict__ h2, f16* __restrict__ l2)
{
    const int z = blockIdx.z;
    const float* x = (z == 0) ? w0 : (z == 1) ? w1 : w2;
    f16* h = (z == 0) ? h0 : (z == 1) ? h1 : h2;
    f16* l = (z == 0) ? l0 : (z == 1) ? l1 : l2;
    size_t base = ((size_t)blockIdx.x * 256 + threadIdx.x) * 8;
#pragma unroll
    for (int j = 0; j < 8; j++)
        split_store16(x[base + j], h + base + j, l + base + j);
}

// Wu transpose -> hi/lo fp16 planes
__global__ __launch_bounds__(256)
void transpose_hilo(const float* __restrict__ in, f16* __restrict__ oh,
                    f16* __restrict__ ol, int R, int C)
{
    __shared__ float t[32][33];
    int c0 = blockIdx.x * 32, r0 = blockIdx.y * 32;
    int x = threadIdx.x & 31, y = (threadIdx.x >> 5) * 4;
#pragma unroll
    for (int i = 0; i < 4; i++)
        t[y + i][x] = in[(size_t)(r0 + y + i) * C + c0 + x];
    __syncthreads();
#pragma unroll
    for (int i = 0; i < 4; i++) {
        size_t o = (size_t)(c0 + y + i) * R + r0 + x;
        split_store16(t[x][y + i], oh + o, ol + o);
    }
}

// per-batch transpose: v fp32 [2048 tok, 256 d] -> vT fp16 [256 d, 2048 tok]
__global__ __launch_bounds__(256)
void transpose_vf16(const float* __restrict__ in, f16* __restrict__ out)
{
    __shared__ float t[32][33];
    const size_t ioff = (size_t)blockIdx.z * 2048 * 256;
    const size_t ooff = (size_t)blockIdx.z * 256 * 2048;
    int c0 = blockIdx.x * 32;   // d block
    int r0 = blockIdx.y * 32;   // tok block
    int x = threadIdx.x & 31, y = (threadIdx.x >> 5) * 4;
#pragma unroll
    for (int i = 0; i < 4; i++)
        t[y + i][x] = in[ioff + (size_t)(r0 + y + i) * 256 + c0 + x];
    __syncthreads();
#pragma unroll
    for (int i = 0; i < 4; i++)
        out[ooff + (size_t)(c0 + y + i) * 2048 + r0 + x] =
            __float2half_rn(t[x][y + i]);
}

// ------------------------- mma.sync batched GEMM -------------------------
// C[M,N] = alpha * A[M,K] @ B[N,K]^T, fp16 K-major operands.
// 64-element K chunks (128B-row tiles, 1024 16B-units per plane,
// 4 units/thread), 3-buf cp.async pipeline.
// TERMS: 1 = Ah*Bh; 3 = + Ah*Bl + Al*Bh.
// OUTMODE: 0 = f32 (Cf), 2 = hi/lo fp16 (Ch,Cl), 3 = hi fp16 (Ch).
// blockIdx.z: A/B element offset z*kzoff, output element offset z*czoff.
template<int OUTMODE, int TERMS>
__global__ __launch_bounds__(256)
void bgemm_mma(int K,
               const f16* __restrict__ Ah, const f16* __restrict__ Al, int lda,
               const f16* __restrict__ Bh, const f16* __restrict__ Bl, int ldb,
               float* __restrict__ Cf, f16* __restrict__ Ch, f16* __restrict__ Cl,
               int ldc, float alpha, long kzoff, long czoff)
{
    extern __shared__ char smem_raw[];
    const uint32_t base = (smem_u32(smem_raw) + 1023) & ~1023u;
    constexpr uint32_t PL = 16384;                 // 128 rows x 64 els x 2B
    constexpr uint32_t BUF = (TERMS == 3) ? 4 * PL : 2 * PL;
    constexpr uint32_t OFF_B = (TERMS == 3) ? 2 * PL : PL;

    const long kz = (long)blockIdx.z * kzoff;
    Ah += kz; Bh += kz;
    if (TERMS == 3) { Al += kz; Bl += kz; }
    const long cz = (long)blockIdx.z * czoff;
    if (OUTMODE == 0) Cf += cz;
    else { Ch += cz; if (OUTMODE == 2) Cl += cz; }

    const int tid  = threadIdx.x;
    const int lane = tid & 31;
    const int warp = tid >> 5;
    const int brow = blockIdx.y * 128;
    const int bcol = blockIdx.x * 128;
    const int wr   = (warp >> 2) * 64;
    const int wc   = (warp & 3) * 32;

    float acc[4][4][4];
#pragma unroll
    for (int mi = 0; mi < 4; mi++)
#pragma unroll
        for (int ni = 0; ni < 4; ni++)
#pragma unroll
            for (int r = 0; r < 4; r++) acc[mi][ni][r] = 0.0f;

    const int nchunk = K >> 6;

    // staging: 1024 16B-units per plane, 4 per thread (u = i*256 + tid)
    auto issue = [&](int c, int buf) {
        const int k0 = c << 6;
        const uint32_t sb = base + buf * BUF;
#pragma unroll
        for (int i = 0; i < 4; i++) {
            const int u = i * 256 + tid;
            const int row = u >> 3, cu = u & 7;
            const uint32_t s = v_off(row, (uint32_t)cu * 16);
            const size_t ga = (size_t)(brow + row) * lda + k0 + cu * 8;
            const size_t gb = (size_t)(bcol + row) * ldb + k0 + cu * 8;
            cpasync16(sb + s, Ah + ga);
            cpasync16(sb + OFF_B + s, Bh + gb);
            if (TERMS == 3) {
                cpasync16(sb + PL + s, Al + ga);
                cpasync16(sb + OFF_B + PL + s, Bl + gb);
            }
        }
        cp_commit();
    };

    issue(0, 0);
    issue(1, 1);

    int bufc = 0;
    for (int c = 0; c < nchunk; c++) {
        if (c + 1 < nchunk) cp_wait1(); else cp_wait0();
        __syncthreads();
        if (c + 2 < nchunk) {
            int nb = bufc + 2; if (nb >= 3) nb -= 3;
            issue(c + 2, nb);
        }

        const uint32_t sb = base + bufc * BUF;
#pragma unroll
        for (int ks = 0; ks < 4; ks++) {
            const uint32_t kb = (uint32_t)(ks * 32 + ((lane >> 4) << 4));
            uint32_t bh[2][4], bl[2][4];
#pragma unroll
            for (int t16 = 0; t16 < 2; t16++) {
                const uint32_t so = v_off(wc + t16 * 16 + (lane & 15), kb);
                ldsm4(bh[t16], sb + OFF_B + so);
                if (TERMS == 3) ldsm4(bl[t16], sb + OFF_B + PL + so);
            }
#pragma unroll
            for (int mi = 0; mi < 4; mi++) {
                uint32_t ah[4], al[4];
                const uint32_t so = v_off(wr + mi * 16 + (lane & 15), kb);
                ldsm4(ah, sb + so);
                if (TERMS == 3) ldsm4(al, sb + PL + so);
#pragma unroll
                for (int ni = 0; ni < 4; ni++) {
                    const int t16 = ni >> 1, sub = ni & 1;
                    const uint32_t bh0 = bh[t16][sub], bh1 = bh[t16][2 + sub];
                    mma16816(acc[mi][ni], ah, bh0, bh1);
                    if (TERMS == 3) {
                        const uint32_t bl0 = bl[t16][sub], bl1 = bl[t16][2 + sub];
                        mma16816(acc[mi][ni], ah, bl0, bl1);
                        mma16816(acc[mi][ni], al, bh0, bh1);
                    }
                }
            }
        }
        if (++bufc == 3) bufc = 0;
    }

#pragma unroll
    for (int mi = 0; mi < 4; mi++) {
#pragma unroll
        for (int half = 0; half < 2; half++) {
            const int row = brow + wr + mi * 16 + (lane >> 2) + half * 8;
#pragma unroll
            for (int ni = 0; ni < 4; ni++) {
                const int col = bcol + wc + ni * 8 + (lane & 3) * 2;
                float v0 = acc[mi][ni][half * 2 + 0] * alpha;
                float v1 = acc[mi][ni][half * 2 + 1] * alpha;
                if (OUTMODE == 0) {
                    float2 o; o.x = v0; o.y = v1;
                    *(float2*)(Cf + (size_t)row * ldc + col) = o;
                } else if (OUTMODE == 3) {
                    *(uint32_t*)(Ch + (size_t)row * ldc + col) = pack_f16x2(v0, v1);
                } else {
                    const size_t off = (size_t)row * ldc + col;
                    f16 h0 = __float2half_rn(v0), h1 = __float2half_rn(v1);
                    *(__half2*)(Ch + off) = __halves2half2(h0, h1);
                    *(__half2*)(Cl + off) = __halves2half2(
                        __float2half_rn(v0 - __half2float(h0)),
                        __float2half_rn(v1 - __half2float(h1)));
                }
            }
        }
    }
}

// ------------------------- split-K reduce + bias -------------------------
__global__ __launch_bounds__(256)
void reduce_add(const float* __restrict__ p, const float* __restrict__ bias,
                float* __restrict__ out)
{
    const size_t i = ((size_t)blockIdx.x * 256 + threadIdx.x) * 4;
    float4 a = *(const float4*)(p + i);
    float4 b = *(const float4*)(p + 2097152 + i);
    const int col = (int)(i & 255);
    float4 o;
    o.x = a.x + b.x + bias[col + 0];
    o.y = a.y + b.y + bias[col + 1];
    o.z = a.z + b.z + bias[col + 2];
    o.w = a.w + b.w + bias[col + 3];
    *(float4*)(out + i) = o;
}

// ------------------------- fused flash attention (1-term fp16) -----------
// grid (16 Q-tiles, 32 b*h). 256 threads, Q-tile 128 rows persistent (64KB).
// K staged as full [64 keys x 256 els] blocks (2 bufs x 32KB, 512B rows),
// V as full [256 d x 64 tok] blocks (2 bufs x 32KB, 128B rows).
// 2 barriers per j-block. Online softmax. (round-14 winner, unchanged)
__global__ __launch_bounds__(256, 1)
void flash_attn(const f16* __restrict__ Qm_, const f16* __restrict__ K_,
                const f16* __restrict__ Vt_,
                f16* __restrict__ Oh_, f16* __restrict__ Ol_)
{
    extern __shared__ char smraw[];
    const uint32_t base = (smem_u32(smraw) + 1023) & ~1023u;
    const uint32_t sQ = base;               // 64KB
    const uint32_t sK = base + 65536;       // 2 bufs x 32KB
    const uint32_t sV = base + 131072;      // 2 bufs x 32KB

    const int tid = threadIdx.x, lane = tid & 31, warp = tid >> 5;
    const int qr0 = blockIdx.x * 128;
    const int b = blockIdx.y >> 3, h = blockIdx.y & 7;
    const int wr = warp * 16;

    const f16* Qg = Qm_ + ((size_t)(b * 2048 + qr0)) * 2048 + h * 256;
    const f16* Kg = K_ + (size_t)b * 2048 * 256;
    const f16* Vg = Vt_ + (size_t)b * 256 * 2048;

    // ---- persistent Q load: 128 rows x 256 fp16 (512B rows), group 0 ----
#pragma unroll
    for (int i = 0; i < 16; i++) {
        int u = i * 256 + tid;
        int row = u >> 5, cu = u & 31;
        cpasync16(sQ + q_off(row, (uint32_t)cu << 4), Qg + (size_t)row * 2048 + cu * 8);
    }
    cp_commit();

    float O[32][4];
#pragma unroll
    for (int nd = 0; nd < 32; nd++)
#pragma unroll
        for (int r = 0; r < 4; r++) O[nd][r] = 0.0f;
    float m2_0 = -1e30f, m2_1 = -1e30f;
    float sm0 = 0.0f, sm1 = 0.0f;

    // K block: [64 keys x 256 els] = 32KB; 2048 units, 8/thread
    auto issueK = [&](int j, int buf) {
        const uint32_t kb = sK + buf * 32768;
#pragma unroll
        for (int i = 0; i < 8; i++) {
            int u = i * 256 + tid;
            int row = u >> 5, cu = u & 31;
            cpasync16(kb + q_off(row, (uint32_t)cu << 4),
                      Kg + (size_t)(j * 64 + row) * 256 + cu * 8);
        }
        cp_commit();
    };
    // V block: [256 d x 64 tok] = 32KB (128B rows); 2048 units, 8/thread
    auto issueV = [&](int j, int buf) {
        const uint32_t vb = sV + buf * 32768;
#pragma unroll
        for (int i = 0; i < 8; i++) {
            int u = i * 256 + tid;
            int row = u >> 3, cu = u & 7;
            cpasync16(vb + v_off(row, (uint32_t)cu << 4),
                      Vg + (size_t)row * 2048 + j * 64 + cu * 8);
        }
        cp_commit();
    };

    issueK(0, 0);
    issueV(0, 0);
    issueK(1, 1);

    for (int j = 0; j < 32; j++) {
        float S[8][4];
#pragma unroll
        for (int ni = 0; ni < 8; ni++)
#pragma unroll
            for (int r = 0; r < 4; r++) S[ni][r] = 0.0f;

        // ---------------- QK^T: full 256 els, one phase ----------------
        if (j < 31) cp_wait2(); else cp_wait1();
        __syncthreads();
        if (j + 1 < 32) issueV(j + 1, (j + 1) & 1);

        {
            const uint32_t kbb = sK + (j & 1) * 32768;
#pragma unroll
            for (int ks = 0; ks < 16; ks++) {
                const uint32_t cb = (uint32_t)(ks * 32 + ((lane >> 4) << 4));
                uint32_t ah[4];
                ldsm4(ah, sQ + q_off(wr + (lane & 15), cb));
#pragma unroll
                for (int t16 = 0; t16 < 4; t16++) {
                    uint32_t bh[4];
                    ldsm4(bh, kbb + q_off(t16 * 16 + (lane & 15), cb));
                    mma16816(S[t16 * 2 + 0], ah, bh[0], bh[2]);
                    mma16816(S[t16 * 2 + 1], ah, bh[1], bh[3]);
                }
            }
        }

        // ---------------- online softmax (warp-local) ----------------
        float rx0 = -1e30f, rx1 = -1e30f;
#pragma unroll
        for (int ni = 0; ni < 8; ni++) {
            rx0 = fmaxf(rx0, fmaxf(S[ni][0], S[ni][1]));
            rx1 = fmaxf(rx1, fmaxf(S[ni][2], S[ni][3]));
        }
        rx0 = fmaxf(rx0, __shfl_xor_sync(0xFFFFFFFFu, rx0, 1));
        rx0 = fmaxf(rx0, __shfl_xor_sync(0xFFFFFFFFu, rx0, 2));
        rx1 = fmaxf(rx1, __shfl_xor_sync(0xFFFFFFFFu, rx1, 1));
        rx1 = fmaxf(rx1, __shfl_xor_sync(0xFFFFFFFFu, rx1, 2));
        const float mn0 = fmaxf(m2_0, rx0), mn1 = fmaxf(m2_1, rx1);
        const float sc0 = ex2(m2_0 - mn0), sc1 = ex2(m2_1 - mn1);
        m2_0 = mn0; m2_1 = mn1;
        if (!__all_sync(0xFFFFFFFFu, (sc0 == 1.0f) && (sc1 == 1.0f))) {
#pragma unroll
            for (int nd = 0; nd < 32; nd++) {
                O[nd][0] *= sc0; O[nd][1] *= sc0;
                O[nd][2] *= sc1; O[nd][3] *= sc1;
            }
        }
        sm0 *= sc0; sm1 *= sc1;

        uint32_t Ph[4][4];
        float bs0 = 0.0f, bs1 = 0.0f;
#pragma unroll
        for (int ni = 0; ni < 8; ni++) {
            const float p0 = ex2(S[ni][0] - mn0), p1 = ex2(S[ni][1] - mn0);
            const float p2 = ex2(S[ni][2] - mn1), p3 = ex2(S[ni][3] - mn1);
            bs0 += p0 + p1; bs1 += p2 + p3;
            const int kk = ni >> 1, a2 = (ni & 1) << 1;
            Ph[kk][a2 + 0] = pack_f16x2(p0, p1);
            Ph[kk][a2 + 1] = pack_f16x2(p2, p3);
        }
        sm0 += bs0; sm1 += bs1;

        // ---------------- PV: full 64 tok, one phase ----------------
        if (j < 31) cp_wait2(); else cp_wait0();
        __syncthreads();
        if (j + 2 < 32) issueK(j + 2, j & 1);

        {
            const uint32_t vb = sV + (j & 1) * 32768;
#pragma unroll
            for (int kk = 0; kk < 4; kk++) {
                const uint32_t cb = (uint32_t)(kk * 32 + ((lane >> 4) << 4));
#pragma unroll
                for (int t16 = 0; t16 < 16; t16++) {
                    uint32_t vh[4];
                    ldsm4(vh, vb + v_off(t16 * 16 + (lane & 15), cb));
                    mma16816(O[t16 * 2 + 0], Ph[kk], vh[0], vh[2]);
                    mma16816(O[t16 * 2 + 1], Ph[kk], vh[1], vh[3]);
                }
            }
        }
    }

    // ---------------- epilogue: normalize, write Pv hi/lo fp16 -----------
    sm0 += __shfl_xor_sync(0xFFFFFFFFu, sm0, 1);
    sm0 += __shfl_xor_sync(0xFFFFFFFFu, sm0, 2);
    sm1 += __shfl_xor_sync(0xFFFFFFFFu, sm1, 1);
    sm1 += __shfl_xor_sync(0xFFFFFFFFu, sm1, 2);
    const float inv0 = 1.0f / sm0, inv1 = 1.0f / sm1;

    const int r = lane >> 2, cq = (lane & 3) * 2;
    const size_t orow0 = ((size_t)(b * 2048 + qr0 + wr + r)) * 2048 + h * 256;
    const size_t orow1 = orow0 + 8 * 2048;
#pragma unroll
    for (int nd = 0; nd < 32; nd++) {
        const int col = nd * 8 + cq;
        const float v0 = O[nd][0] * inv0, v1 = O[nd][1] * inv0;
        const float v2 = O[nd][2] * inv1, v3 = O[nd][3] * inv1;
        f16 h0 = __float2half_rn(v0), h1 = __float2half_rn(v1);
        f16 h2 = __float2half_rn(v2), h3 = __float2half_rn(v3);
        *(__half2*)(Oh_ + orow0 + col) = __halves2half2(h0, h1);
        *(__half2*)(Ol_ + orow0 + col) = __halves2half2(
            __float2half_rn(v0 - __half2float(h0)),
            __float2half_rn(v1 - __half2float(h1)));
        *(__half2*)(Oh_ + orow1 + col) = __halves2half2(h2, h3);
        *(__half2*)(Ol_ + orow1 + col) = __halves2half2(
            __float2half_rn(v2 - __half2float(h2)),
            __float2half_rn(v3 - __half2float(h3)));
    }
}

// ------------------------- launcher --------------------------------------
extern "C" void kernel_launch(void* const* d_in, const int* in_sizes, int n_in,
                              void* d_out, int out_size)
{
    const float* q  = (const float*)d_in[0];
    const float* k  = (const float*)d_in[1];
    const float* v  = (const float*)d_in[2];
    const float* Wq = (const float*)d_in[3];
    const float* Wk = (const float*)d_in[4];
    const float* Wv = (const float*)d_in[5];
    const float* Wu = (const float*)d_in[6];
    const float* bu = (const float*)d_in[7];
    float* out = (float*)d_out;

#define SYM(p, s) void* p##_; cudaGetSymbolAddress(&p##_, s); auto* p = (decltype(&s[0]))p##_
    SYM(qh, g_qh); SYM(kh, g_kh);
    SYM(Wqh, g_Wqh); SYM(Wql, g_Wql);
    SYM(Wkh, g_Wkh); SYM(Wkl, g_Wkl);
    SYM(Wvh, g_Wvh); SYM(Wvl, g_Wvl);
    SYM(WuTh, g_WuTh); SYM(WuTl, g_WuTl);
    SYM(MT, g_MT); SYM(NTh, g_NTh); SYM(NTl, g_NTl);
    SYM(vT, g_vT); SYM(Qm, g_Qm);
    SYM(Oh, g_Oh); SYM(Ol, g_Ol);
    SYM(Part, g_Part);
#undef SYM

    const int SMEM1 = 3 * 32768 + 1024;     // 1-term: 3 bufs x 32KB
    const int SMEM3 = 3 * 65536 + 1024;     // 3-term: 3 bufs x 64KB
    cudaFuncSetAttribute(bgemm_mma<3, 1>, cudaFuncAttributeMaxDynamicSharedMemorySize, SMEM1);
    cudaFuncSetAttribute(bgemm_mma<3, 3>, cudaFuncAttributeMaxDynamicSharedMemorySize, SMEM3);
    cudaFuncSetAttribute(bgemm_mma<2, 3>, cudaFuncAttributeMaxDynamicSharedMemorySize, SMEM3);
    cudaFuncSetAttribute(bgemm_mma<0, 3>, cudaFuncAttributeMaxDynamicSharedMemorySize, SMEM3);
    const int FSMEM = 196608 + 1024;        // Q 64K + K 64K + V 64K
    cudaFuncSetAttribute(flash_attn, cudaFuncAttributeMaxDynamicSharedMemorySize, FSMEM);

    // fold softmax scale (1/16) and log2(e) into the Q projection
    const float alpha_q = 0.0625f * 1.44269504088896340736f;

    // 1. q,k -> fp16 (one launch)
    convert2<<<dim3(1024, 1, 2), 256>>>(q, k, qh, kh);

    // 2. Wq/Wk/Wv -> hi/lo fp16 planes (no transpose); Wu -> transposed hi/lo
    convhl3<<<dim3(256, 1, 3), 256>>>(Wq, Wk, Wv,
        Wqh, Wql, Wkh, Wkl, Wvh, Wvl);
    transpose_hilo<<<dim3(8, 64, 1), 256>>>(Wu, WuTh, WuTl, 2048, 256);

    // 3. v -> per-batch transposed fp16 vT [256 d, 2048 tok]
    transpose_vf16<<<dim3(8, 64, 4), 256>>>(v, vT);

    // 4. M^T[h*256+j][i] = sum_d Wk[j][h*256+d] Wq[i][h*256+d]  (3-term)
    bgemm_mma<3, 3><<<dim3(2, 2, 8), 256, SMEM3>>>(256,
        Wkh, Wkl, 2048, Wqh, Wql, 2048, nullptr, MT, nullptr, 256, 1.0f,
        256, 256L * 256);

    // 5. N^T[j][h*256+i] = sum_d WuT[j][h*256+d] Wv[i][h*256+d]  (3-term, hi/lo out)
    bgemm_mma<2, 3><<<dim3(2, 2, 8), 256, SMEM3>>>(256,
        WuTh, WuTl, 2048, Wvh, Wvl, 2048, nullptr, NTh, NTl, 2048, 1.0f,
        256, 256);

    // 6. Qm = q @ M (pre-scaled): [8192,2048] = [8192,256] @ [2048,256]^T
    bgemm_mma<3, 1><<<dim3(16, 64, 1), 256, SMEM1>>>(256,
        qh, nullptr, 256, MT, nullptr, 256, nullptr, Qm, nullptr, 2048, alpha_q,
        0, 0);

    // 7. fused attention vs raw k / vT; writes Pv hi/lo
    flash_attn<<<dim3(16, 32), 256, FSMEM>>>(Qm, kh, vT, Oh, Ol);

    // 8. out-projection, split-K=2: partials = Pv @ N  (3-term hi/lo)
    bgemm_mma<0, 3><<<dim3(2, 64, 2), 256, SMEM3>>>(1024,
        Oh, Ol, 2048, NTh, NTl, 2048, Part, nullptr, nullptr, 256, 1.0f,
        1024, 8192L * 256);

    // 9. out = part0 + part1 + bu
    reduce_add<<<2048, 256>>>(Part, bu, out);
}